// round 7
// baseline (speedup 1.0000x reference)
#include <cuda_runtime.h>
#include <cuda_bf16.h>
#include <math.h>
#include <stdint.h>

// ---------------- problem constants ----------------
#define BATCH 512
#define NPRIM 32
#define NCLASS 10

// ---------------- scratch (static device memory; no allocs allowed) ----------------
// conv1 output as bf16 hi/lo split, layout [b][pixel(400)][ic(256)]
__device__ __align__(256) unsigned short g_h1h[BATCH * 400 * 256];   // 100 MB
__device__ __align__(256) unsigned short g_h1l[BATCH * 400 * 256];   // 100 MB
// prim weights prepacked: [kpos25][chunk4][oc256][ic64] bf16 hi/lo
__device__ __align__(256) unsigned short g_Wph[25 * 4 * 256 * 64];   // 3.3 MB
__device__ __align__(256) unsigned short g_Wpl[25 * 4 * 256 * 64];   // 3.3 MB
__device__ float g_cwT[8 * 25 * 256];                    // conv_w transposed [c*25+k][oc]
__device__ float g_p[BATCH * NPRIM * 8 * 64];            // primary caps acts [b][i][a][pos]
__device__ float g_votes2[BATCH * 4 * 32 * 256];         // [b][pos][i][oc]
__device__ float g_c[BATCH * 32 * 8 * 4];                // [b][o][a][pos]
__device__ float g_masked[BATCH * 160];
__device__ float g_r1[BATCH * 512];
__device__ float g_r2[BATCH * 1024];

// ---------------- f32x2 helpers ----------------
__device__ __forceinline__ unsigned long long bcast2(float v) {
    unsigned long long r;
    asm("mov.b64 %0, {%1, %1};" : "=l"(r) : "f"(v));
    return r;
}
__device__ __forceinline__ void fma2(unsigned long long& acc, unsigned long long a,
                                     unsigned long long b) {
    asm("fma.rn.f32x2 %0, %1, %2, %0;" : "+l"(acc) : "l"(a), "l"(b));
}
__device__ __forceinline__ float2 unpk(unsigned long long v) {
    float2 r;
    asm("mov.b64 {%0, %1}, %2;" : "=f"(r.x), "=f"(r.y) : "l"(v));
    return r;
}

// ---------------- cp.async helpers ----------------
__device__ __forceinline__ void cp16(void* smem, const void* g) {
    unsigned s;
    asm("{ .reg .u64 t; cvta.to.shared.u64 t, %1; cvt.u32.u64 %0, t; }"
        : "=r"(s) : "l"(smem));
    asm volatile("cp.async.cg.shared.global [%0], [%1], 16;" :: "r"(s), "l"(g));
}
__device__ __forceinline__ void cp_commit() { asm volatile("cp.async.commit_group;"); }
__device__ __forceinline__ void cp_wait0() {
    asm volatile("cp.async.wait_group 0;" ::: "memory");
}
__device__ __forceinline__ void cp_wait1() {
    asm volatile("cp.async.wait_group 1;" ::: "memory");
}

// ---------------- mma.sync bf16 + ldmatrix (sm_80+ legacy tensor path) ----------------
__device__ __forceinline__ void mma_bf16(float* d, const uint32_t* a, uint32_t b0,
                                         uint32_t b1) {
    asm volatile(
        "mma.sync.aligned.m16n8k16.row.col.f32.bf16.bf16.f32 "
        "{%0,%1,%2,%3}, {%4,%5,%6,%7}, {%8,%9}, {%0,%1,%2,%3};"
        : "+f"(d[0]), "+f"(d[1]), "+f"(d[2]), "+f"(d[3])
        : "r"(a[0]), "r"(a[1]), "r"(a[2]), "r"(a[3]), "r"(b0), "r"(b1));
}
__device__ __forceinline__ void ldm_x4(uint32_t* r, uint32_t addr) {
    asm volatile("ldmatrix.sync.aligned.m8n8.x4.shared.b16 {%0,%1,%2,%3}, [%4];"
        : "=r"(r[0]), "=r"(r[1]), "=r"(r[2]), "=r"(r[3]) : "r"(addr));
}
__device__ __forceinline__ uint32_t smem_u32(const void* p) {
    uint32_t a;
    asm("{ .reg .u64 t; cvta.to.shared.u64 t, %1; cvt.u32.u64 %0, t; }" : "=r"(a) : "l"(p));
    return a;
}

// ---------------- weight transpose: w[oc][ick] -> wt[ick][oc] ----------------
__global__ void transpose_oc(const float* __restrict__ w, float* __restrict__ wt,
                             int OC, int ICK) {
    int idx = blockIdx.x * 256 + threadIdx.x;
    if (idx >= OC * ICK) return;
    int ick = idx / OC, oc = idx % OC;
    wt[idx] = w[oc * ICK + ick];
}

// ---------------- prepack prim weights: [kpos][chunk][oc][ic64] bf16 hi/lo ------------
__global__ void prepack_W(const float* __restrict__ w) {
    int idx = blockIdx.x * 256 + threadIdx.x;
    if (idx >= 25 * 4 * 256 * 64) return;
    int ic = idx & 63;
    int oc = (idx >> 6) & 255;
    int chunk = (idx >> 14) & 3;
    int kpos = idx >> 16;
    float v = w[oc * 6400 + (chunk * 64 + ic) * 25 + kpos];
    __nv_bfloat16 hi = __float2bfloat16(v);
    __nv_bfloat16 lo = __float2bfloat16(v - __bfloat162float(hi));
    g_Wph[idx] = __bfloat16_as_ushort(hi);
    g_Wpl[idx] = __bfloat16_as_ushort(lo);
}

// ---------------- conv1 + relu (f32x2), writes bf16 hi/lo [b][pix][ic] ----------------
__global__ __launch_bounds__(256) void conv1_kernel(
    const float* __restrict__ x, const float* __restrict__ w,
    const float* __restrict__ bias) {
    __shared__ float sx[784];
    __shared__ float sw2[81 * 16];
    __shared__ float sb[16];
    int b = blockIdx.x, g = blockIdx.y, tid = threadIdx.x;
    for (int i = tid; i < 784; i += 256) sx[i] = x[b * 784 + i];
    for (int i = tid; i < 81 * 16; i += 256) {
        int k = i >> 4, c = i & 15;
        sw2[i] = w[(g * 16 + c) * 81 + k];
    }
    if (tid < 16) sb[tid] = bias[g * 16 + tid];
    __syncthreads();

    int p0 = tid;
    int p1 = tid + 256;
    bool has1 = (p1 < 400);
    int p1c = has1 ? p1 : 0;
    int y0 = p0 / 20, x0 = p0 % 20;
    int y1 = p1c / 20, x1 = p1c % 20;
    unsigned long long a0[8], a1[8];
#pragma unroll
    for (int j = 0; j < 8; j++) { a0[j] = 0ULL; a1[j] = 0ULL; }
#pragma unroll
    for (int kh = 0; kh < 9; kh++) {
#pragma unroll
        for (int kw = 0; kw < 9; kw++) {
            unsigned long long d0 = bcast2(sx[(y0 + kh) * 28 + x0 + kw]);
            unsigned long long d1 = bcast2(sx[(y1 + kh) * 28 + x1 + kw]);
            int k = kh * 9 + kw;
            const ulonglong2* wp = (const ulonglong2*)&sw2[k * 16];
            ulonglong2 wA = wp[0], wB = wp[1], wC = wp[2], wD = wp[3];
            fma2(a0[0], d0, wA.x); fma2(a0[1], d0, wA.y);
            fma2(a0[2], d0, wB.x); fma2(a0[3], d0, wB.y);
            fma2(a0[4], d0, wC.x); fma2(a0[5], d0, wC.y);
            fma2(a0[6], d0, wD.x); fma2(a0[7], d0, wD.y);
            fma2(a1[0], d1, wA.x); fma2(a1[1], d1, wA.y);
            fma2(a1[2], d1, wB.x); fma2(a1[3], d1, wB.y);
            fma2(a1[4], d1, wC.x); fma2(a1[5], d1, wC.y);
            fma2(a1[6], d1, wD.x); fma2(a1[7], d1, wD.y);
        }
    }
#pragma unroll
    for (int half = 0; half < 2; half++) {
        if (half == 1 && !has1) break;
        int p = half ? p1 : p0;
        unsigned long long* A = half ? a1 : a0;
        uint32_t hw[8], lw[8];
#pragma unroll
        for (int j = 0; j < 8; j++) {
            float2 v = unpk(A[j]);
            float r0 = v.x + sb[2 * j];     r0 = r0 > 0.f ? r0 : 0.f;
            float r1 = v.y + sb[2 * j + 1]; r1 = r1 > 0.f ? r1 : 0.f;
            __nv_bfloat16 h0 = __float2bfloat16(r0);
            __nv_bfloat16 h1 = __float2bfloat16(r1);
            __nv_bfloat16 l0 = __float2bfloat16(r0 - __bfloat162float(h0));
            __nv_bfloat16 l1 = __float2bfloat16(r1 - __bfloat162float(h1));
            hw[j] = (uint32_t)__bfloat16_as_ushort(h0) |
                    ((uint32_t)__bfloat16_as_ushort(h1) << 16);
            lw[j] = (uint32_t)__bfloat16_as_ushort(l0) |
                    ((uint32_t)__bfloat16_as_ushort(l1) << 16);
        }
        size_t base = ((size_t)b * 400 + p) * 256 + g * 16;
        uint4* dh = (uint4*)&g_h1h[base];
        uint4* dl = (uint4*)&g_h1l[base];
        dh[0] = make_uint4(hw[0], hw[1], hw[2], hw[3]);
        dh[1] = make_uint4(hw[4], hw[5], hw[6], hw[7]);
        dl[0] = make_uint4(lw[0], lw[1], lw[2], lw[3]);
        dl[1] = make_uint4(lw[4], lw[5], lw[6], lw[7]);
    }
}

// ---------------- primary caps conv via mma.sync + ldmatrix, 3-stage pipeline ---------
// grid 512 (= 256 batch-pairs x 2 oc-halves of 128), 512 threads (16 warps:
// warpM 0/1 x warpN 0..7 of 16 oc). 100 k-steps (kpos x ic-chunk of 64).
// Per buffer: A hi/lo 128x144 + B hi/lo 128x144 = 73728 B; 3 buffers = 221184 B.
#define PITCH 144
#define OFF_AH 0
#define OFF_AL 18432
#define OFF_BH 36864
#define OFF_BL 55296
#define PBUF 73728
#define PRIM_SMEM (3 * PBUF)           // 221184

extern __shared__ char psmem[];

__device__ __forceinline__ void prim_load_step(int buf, int s, int tid, int b0, int nHalf) {
    int kpos = s >> 2, chunk = s & 3;
    int kh = kpos / 5, kw = kpos - kh * 5;
    char* base = psmem + buf * PBUF;
    // A: 128 rows x 128B from g_h1h/g_h1l
#pragma unroll
    for (int ii = 0; ii < 2; ii++) {
        int i = tid + ii * 512;          // 0..1023
        int r = i >> 3, seg = i & 7;
        int batch = r >> 6, pos = r & 63;
        int y = pos >> 3, xx = pos & 7;
        int pix = (2 * y + kh) * 20 + 2 * xx + kw;
        size_t src = ((size_t)(b0 + batch) * 400 + pix) * 256 + chunk * 64 + seg * 8;
        char* d = base + r * PITCH + seg * 16;
        cp16(d + OFF_AH, &g_h1h[src]);
        cp16(d + OFF_AL, &g_h1l[src]);
    }
    // B: 128 rows (this block's oc half) x 128B from g_Wph/g_Wpl
    size_t wbase = (size_t)s * 16384 + (size_t)nHalf * 8192;
#pragma unroll
    for (int ii = 0; ii < 2; ii++) {
        int i = tid + ii * 512;          // 0..1023
        int r = i >> 3, seg = i & 7;
        size_t src = wbase + r * 64 + seg * 8;
        char* d = base + r * PITCH + seg * 16;
        cp16(d + OFF_BH, &g_Wph[src]);
        cp16(d + OFF_BL, &g_Wpl[src]);
    }
}

__global__ __launch_bounds__(512, 1) void prim_mma_kernel(const float* __restrict__ prim_bias) {
    int tid = threadIdx.x;
    int pairIdx = blockIdx.x >> 1;
    int nHalf = blockIdx.x & 1;
    int b0 = pairIdx * 2;
    int wid = tid >> 5, lane = tid & 31;
    int g = lane >> 2, c = lane & 3;
    int warpM = wid & 1;       // rows 0-63 / 64-127
    int warpN = wid >> 1;      // 0..7 -> 16-oc slice within this block's 128

    uint32_t sbase = smem_u32(psmem);
    uint32_t aOff = (uint32_t)(warpM * 64 + (lane & 15)) * PITCH + ((lane >> 4) << 4);
    uint32_t bRow = (uint32_t)(warpN * 16 + (lane & 7) + ((lane & 16) >> 1));
    uint32_t bOff = bRow * PITCH + ((lane & 8) ? 16u : 0u);

    float acc[4][2][4];
#pragma unroll
    for (int mt = 0; mt < 4; mt++)
#pragma unroll
        for (int nt = 0; nt < 2; nt++)
#pragma unroll
            for (int q = 0; q < 4; q++) acc[mt][nt][q] = 0.f;

    // prologue: 2 steps in flight
    prim_load_step(0, 0, tid, b0, nHalf);
    cp_commit();
    prim_load_step(1, 1, tid, b0, nHalf);
    cp_commit();

    for (int s = 0; s < 100; s++) {
        int buf = s - (s / 3) * 3;        // s % 3
        if (s + 1 < 100) cp_wait1(); else cp_wait0();
        __syncthreads();                  // buf ready; all warps done with buf (s+2)%3
        if (s + 2 < 100) {
            int nb = buf + 2; if (nb >= 3) nb -= 3;
            prim_load_step(nb, s + 2, tid, b0, nHalf);
            cp_commit();
        }
        uint32_t tbase = sbase + buf * PBUF;
        uint32_t aBase = tbase + OFF_AH + aOff;
        uint32_t bBase = tbase + OFF_BH + bOff;
#pragma unroll
        for (int kk = 0; kk < 4; kk++) {
            uint32_t bh[4], bl[4];
            ldm_x4(bh, bBase + kk * 32);
            ldm_x4(bl, bBase + (OFF_BL - OFF_BH) + kk * 32);
#pragma unroll
            for (int mt = 0; mt < 4; mt++) {
                uint32_t ah[4], al[4];
                ldm_x4(ah, aBase + mt * (16 * PITCH) + kk * 32);
                ldm_x4(al, aBase + (OFF_AL - OFF_AH) + mt * (16 * PITCH) + kk * 32);
#pragma unroll
                for (int nt = 0; nt < 2; nt++) {
                    float* d = acc[mt][nt];
                    mma_bf16(d, ah, bh[nt * 2], bh[nt * 2 + 1]);
                    mma_bf16(d, ah, bl[nt * 2], bl[nt * 2 + 1]);
                    mma_bf16(d, al, bh[nt * 2], bh[nt * 2 + 1]);
                }
            }
        }
    }

    // fused epilogue: route=1/32, +bias, squash over 8 atoms (quad shfl reduction)
    int b_ = b0 + warpM;
#pragma unroll
    for (int mt = 0; mt < 4; mt++) {
        int pos1 = mt * 16 + g;
        int pos2 = pos1 + 8;
#pragma unroll
        for (int nt = 0; nt < 2; nt++) {
            int caps = nHalf * 16 + warpN * 2 + nt;
            float bv0 = __ldg(&prim_bias[caps * 8 + 2 * c]);
            float bv1 = __ldg(&prim_bias[caps * 8 + 2 * c + 1]);
            float v0 = acc[mt][nt][0] * (1.f / 32.f) + bv0;
            float v1 = acc[mt][nt][1] * (1.f / 32.f) + bv1;
            float v2 = acc[mt][nt][2] * (1.f / 32.f) + bv0;
            float v3 = acc[mt][nt][3] * (1.f / 32.f) + bv1;
            float na = v0 * v0 + v1 * v1;
            float nb = v2 * v2 + v3 * v3;
            na += __shfl_xor_sync(0xFFFFFFFFu, na, 1);
            na += __shfl_xor_sync(0xFFFFFFFFu, na, 2);
            nb += __shfl_xor_sync(0xFFFFFFFFu, nb, 1);
            nb += __shfl_xor_sync(0xFFFFFFFFu, nb, 2);
            float fa = (na / (1.f + na)) * rsqrtf(na + 1e-8f);
            float fb = (nb / (1.f + nb)) * rsqrtf(nb + 1e-8f);
            size_t base = ((size_t)(b_ * 32 + caps) * 8) * 64;
            g_p[base + (2 * c) * 64 + pos1] = v0 * fa;
            g_p[base + (2 * c + 1) * 64 + pos1] = v1 * fa;
            g_p[base + (2 * c) * 64 + pos2] = v2 * fb;
            g_p[base + (2 * c + 1) * 64 + pos2] = v3 * fb;
        }
    }
}

// ---------------- conv-caps votes (f32x2) ----------------
__global__ __launch_bounds__(256) void cc_votes_kernel() {
    extern __shared__ float smem[];
    float* sp = smem;
    float* swc = smem + 16384;
    int b = blockIdx.x, tid = threadIdx.x;
    for (int idx = tid; idx < 16384; idx += 256) sp[idx] = g_p[b * 16384 + idx];

    int ocg = tid & 7;
    int i = tid >> 3;
    for (int occ = 0; occ < 4; occ++) {
        __syncthreads();
        for (int idx = tid; idx < 12800; idx += 256)
            swc[idx] = g_cwT[(idx >> 6) * 256 + occ * 64 + (idx & 63)];
        __syncthreads();
        unsigned long long acc[4][4];
#pragma unroll
        for (int p = 0; p < 4; p++)
#pragma unroll
            for (int j = 0; j < 4; j++) acc[p][j] = 0ULL;
#pragma unroll
        for (int cc = 0; cc < 8; cc++) {
            const float* spc = &sp[(i * 8 + cc) * 64];
#pragma unroll
            for (int kh = 0; kh < 5; kh++) {
#pragma unroll
                for (int kw = 0; kw < 5; kw++) {
                    unsigned long long d00 = bcast2(spc[kh * 8 + kw]);
                    unsigned long long d01 = bcast2(spc[kh * 8 + kw + 2]);
                    unsigned long long d10 = bcast2(spc[(kh + 2) * 8 + kw]);
                    unsigned long long d11 = bcast2(spc[(kh + 2) * 8 + kw + 2]);
                    const ulonglong2* wp =
                        (const ulonglong2*)&swc[(cc * 25 + kh * 5 + kw) * 64 + ocg * 8];
                    ulonglong2 wA = wp[0], wB = wp[1];
                    fma2(acc[0][0], d00, wA.x); fma2(acc[0][1], d00, wA.y);
                    fma2(acc[0][2], d00, wB.x); fma2(acc[0][3], d00, wB.y);
                    fma2(acc[1][0], d01, wA.x); fma2(acc[1][1], d01, wA.y);
                    fma2(acc[1][2], d01, wB.x); fma2(acc[1][3], d01, wB.y);
                    fma2(acc[2][0], d10, wA.x); fma2(acc[2][1], d10, wA.y);
                    fma2(acc[2][2], d10, wB.x); fma2(acc[2][3], d10, wB.y);
                    fma2(acc[3][0], d11, wA.x); fma2(acc[3][1], d11, wA.y);
                    fma2(acc[3][2], d11, wB.x); fma2(acc[3][3], d11, wB.y);
                }
            }
        }
#pragma unroll
        for (int p = 0; p < 4; p++) {
            float2 q0 = unpk(acc[p][0]), q1 = unpk(acc[p][1]);
            float2 q2 = unpk(acc[p][2]), q3 = unpk(acc[p][3]);
            float4* dst = (float4*)&g_votes2[((b * 4 + p) * 32 + i) * 256 + occ * 64 + ocg * 8];
            dst[0] = make_float4(q0.x, q0.y, q1.x, q1.y);
            dst[1] = make_float4(q2.x, q2.y, q3.x, q3.y);
        }
    }
}

// ---------------- conv-caps routing (3 iters) ----------------
__global__ __launch_bounds__(256) void cc_routing_kernel(const float* __restrict__ conv_bias) {
    __shared__ float sv[8192];
    __shared__ float slog[1024];
    __shared__ float sroute[1024];
    __shared__ float spre[256];
    __shared__ float sact[256];
    int blk = blockIdx.x;
    int b = blk >> 2, pos = blk & 3;
    int tid = threadIdx.x;
    for (int idx = tid; idx < 8192; idx += 256)
        sv[idx] = g_votes2[(b * 4 + pos) * 8192 + idx];
    for (int e = tid; e < 1024; e += 256) slog[e] = 0.f;
    __syncthreads();

    for (int it = 0; it < 3; it++) {
        if (tid < 32) {
            int i = tid;
            float m = slog[i * 32];
            for (int o = 1; o < 32; o++) m = fmaxf(m, slog[i * 32 + o]);
            float z = 0.f;
            for (int o = 0; o < 32; o++) {
                float e = expf(slog[i * 32 + o] - m);
                sroute[i * 32 + o] = e;
                z += e;
            }
            float inv = 1.f / z;
            for (int o = 0; o < 32; o++) sroute[i * 32 + o] *= inv;
        }
        __syncthreads();
        {
            int o = tid >> 3, a = tid & 7;
            float s = conv_bias[o * 8 + a];
            for (int i = 0; i < 32; i++)
                s += sroute[i * 32 + o] * sv[(i * 32 + o) * 8 + a];
            spre[tid] = s;
        }
        __syncthreads();
        {
            int o = tid >> 3;
            float n2 = 0.f;
#pragma unroll
            for (int a = 0; a < 8; a++) { float v = spre[o * 8 + a]; n2 += v * v; }
            float f = (n2 / (1.f + n2)) * rsqrtf(n2 + 1e-8f);
            sact[tid] = spre[tid] * f;
        }
        __syncthreads();
        if (it < 2) {
            for (int e = tid; e < 1024; e += 256) {
                int o = e & 31;
                float d = 0.f;
#pragma unroll
                for (int a = 0; a < 8; a++) d += sv[e * 8 + a] * sact[o * 8 + a];
                slog[e] += d;
            }
            __syncthreads();
        }
    }
    {
        int o = tid >> 3, a = tid & 7;
        g_c[((b * 32 + o) * 8 + a) * 4 + pos] = sact[tid];
    }
}

// ---------------- digit caps: votes + routing + mask ----------------
__global__ __launch_bounds__(256) void digit_kernel(
    const float* __restrict__ digit_w, const float* __restrict__ digit_bias,
    const float* __restrict__ y, float* __restrict__ out_dcap) {
    __shared__ float smem[11264];
    float* sc = smem;
    float* sdw = smem + 1024;
    float* sv = smem + 6144;
    int b = blockIdx.x, tid = threadIdx.x;
    for (int idx = tid; idx < 1024; idx += 256) sc[idx] = g_c[b * 1024 + idx];
    for (int idx = tid; idx < 5120; idx += 256) sdw[idx] = digit_w[idx];
    __syncthreads();
    for (int idx = tid; idx < 5120; idx += 256) {
        int i = idx / 160, oa = idx % 160;
        float s = 0.f;
        const float* ci = &sc[i * 32];
        const float* wv = &sdw[oa * 32];
#pragma unroll
        for (int z = 0; z < 32; z++) s += ci[z] * wv[z];
        sv[(i * 10 + (oa >> 4)) * 16 + (oa & 15)] = s;
    }
    __syncthreads();
    float* slog = smem;
    float* sroute = smem + 320;
    float* spre = smem + 640;
    float* sact = smem + 800;
    float* sbias = smem + 960;
    for (int e = tid; e < 320; e += 256) slog[e] = 0.f;
    if (tid < 160) sbias[tid] = digit_bias[tid];
    __syncthreads();

    for (int it = 0; it < 3; it++) {
        if (tid < 32) {
            int i = tid;
            float m = slog[i * 10];
            for (int o = 1; o < 10; o++) m = fmaxf(m, slog[i * 10 + o]);
            float z = 0.f;
            for (int o = 0; o < 10; o++) {
                float e = expf(slog[i * 10 + o] - m);
                sroute[i * 10 + o] = e;
                z += e;
            }
            float inv = 1.f / z;
            for (int o = 0; o < 10; o++) sroute[i * 10 + o] *= inv;
        }
        __syncthreads();
        if (tid < 160) {
            int o = tid >> 4, a = tid & 15;
            float s = sbias[tid];
            for (int i = 0; i < 32; i++)
                s += sroute[i * 10 + o] * sv[(i * 10 + o) * 16 + a];
            spre[tid] = s;
        }
        __syncthreads();
        if (tid < 160) {
            int o = tid >> 4;
            float n2 = 0.f;
#pragma unroll
            for (int a = 0; a < 16; a++) { float v = spre[o * 16 + a]; n2 += v * v; }
            float f = (n2 / (1.f + n2)) * rsqrtf(n2 + 1e-8f);
            sact[tid] = spre[tid] * f;
        }
        __syncthreads();
        if (it < 2) {
            for (int e = tid; e < 320; e += 256) {
                int o = e % 10;
                float d = 0.f;
#pragma unroll
                for (int a = 0; a < 16; a++) d += sv[e * 16 + a] * sact[o * 16 + a];
                slog[e] += d;
            }
            __syncthreads();
        }
    }
    if (tid < 160) {
        int o = tid >> 4;
        float v = sact[tid];
        out_dcap[b * 160 + tid] = v;
        g_masked[b * 160 + tid] = v * y[b * 10 + o];
    }
}

// ---------------- FC: C = act(A @ W + bias) ----------------
template <int ACT>
__global__ __launch_bounds__(256) void fc_kernel(
    const float* __restrict__ A, const float* __restrict__ W,
    const float* __restrict__ bias, float* __restrict__ C,
    int M, int K, int N) {
    __shared__ float As[16][64];
    __shared__ float Ws[16][64];
    int m0 = blockIdx.y * 64, n0 = blockIdx.x * 64;
    int tid = threadIdx.x;
    int tr = tid >> 4, tc = tid & 15;
    float acc[4][4];
#pragma unroll
    for (int i = 0; i < 4; i++)
#pragma unroll
        for (int j = 0; j < 4; j++) acc[i][j] = 0.f;

    for (int k0 = 0; k0 < K; k0 += 16) {
        for (int l = tid; l < 1024; l += 256) {
            int ml = l >> 4, kl = l & 15;
            As[kl][ml] = A[(m0 + ml) * K + k0 + kl];
        }
        for (int l = tid; l < 1024; l += 256) {
            int kl = l >> 6, nl = l & 63;
            int n = n0 + nl;
            Ws[kl][nl] = (n < N) ? W[(k0 + kl) * N + n] : 0.f;
        }
        __syncthreads();
#pragma unroll
        for (int kk = 0; kk < 16; kk++) {
            float4 a4 = *(const float4*)&As[kk][tr * 4];
            float4 b4 = *(const float4*)&Ws[kk][tc * 4];
            float av[4] = {a4.x, a4.y, a4.z, a4.w};
            float bv[4] = {b4.x, b4.y, b4.z, b4.w};
#pragma unroll
            for (int i = 0; i < 4; i++)
#pragma unroll
                for (int j = 0; j < 4; j++) acc[i][j] += av[i] * bv[j];
        }
        __syncthreads();
    }
#pragma unroll
    for (int i = 0; i < 4; i++) {
        int m = m0 + tr * 4 + i;
#pragma unroll
        for (int j = 0; j < 4; j++) {
            int n = n0 + tc * 4 + j;
            if (n < N) {
                float v = acc[i][j] + bias[n];
                if (ACT == 1) v = v > 0.f ? v : 0.f;
                if (ACT == 2) v = 1.f / (1.f + expf(-v));
                C[m * N + n] = v;
            }
        }
    }
}

// ---------------- launcher ----------------
extern "C" void kernel_launch(void* const* d_in, const int* in_sizes, int n_in,
                              void* d_out, int out_size) {
    const float* x = (const float*)d_in[0];
    const float* y = (const float*)d_in[1];
    const float* conv1_w = (const float*)d_in[2];
    const float* conv1_b = (const float*)d_in[3];
    const float* prim_w = (const float*)d_in[4];
    const float* prim_bias = (const float*)d_in[5];
    const float* conv_w = (const float*)d_in[6];
    const float* conv_bias = (const float*)d_in[7];
    const float* digit_w = (const float*)d_in[8];
    const float* digit_bias = (const float*)d_in[9];
    const float* fc1_w = (const float*)d_in[10];
    const float* fc1_b = (const float*)d_in[11];
    const float* fc2_w = (const float*)d_in[12];
    const float* fc2_b = (const float*)d_in[13];
    const float* fc3_w = (const float*)d_in[14];
    const float* fc3_b = (const float*)d_in[15];
    float* out = (float*)d_out;              // [0:81920) dcap, [81920:483328) recon

    static float *p_masked = nullptr, *p_r1 = nullptr, *p_r2 = nullptr;
    static float *g_cwT_p = nullptr;
    static bool attrs_set = false;
    if (!p_masked) {
        cudaGetSymbolAddress((void**)&p_masked, g_masked);
        cudaGetSymbolAddress((void**)&p_r1, g_r1);
        cudaGetSymbolAddress((void**)&p_r2, g_r2);
        cudaGetSymbolAddress((void**)&g_cwT_p, g_cwT);
    }
    if (!attrs_set) {
        cudaFuncSetAttribute(prim_mma_kernel, cudaFuncAttributeMaxDynamicSharedMemorySize,
                             PRIM_SMEM);
        cudaFuncSetAttribute(cc_votes_kernel, cudaFuncAttributeMaxDynamicSharedMemorySize,
                             (16384 + 12800) * 4);
        attrs_set = true;
    }

    // weight prep
    prepack_W<<<(25 * 4 * 256 * 64 + 255) / 256, 256>>>(prim_w);
    transpose_oc<<<200, 256>>>(conv_w, g_cwT_p, 256, 200);

    // conv1 + relu (writes bf16 hi/lo, pixel-major)
    conv1_kernel<<<dim3(512, 16), 256>>>(x, conv1_w, conv1_b);

    // primary caps conv via mma.sync + ldmatrix, 3-stage pipeline + fused squash
    prim_mma_kernel<<<512, 512, PRIM_SMEM>>>(prim_bias);

    // conv caps votes
    cc_votes_kernel<<<512, 256, (16384 + 12800) * 4>>>();

    // conv caps routing
    cc_routing_kernel<<<2048, 256>>>(conv_bias);

    // digit caps
    digit_kernel<<<512, 256>>>(digit_w, digit_bias, y, out);

    // FC reconstruction chain
    fc_kernel<1><<<dim3(8, 8), 256>>>(p_masked, fc1_w, fc1_b, p_r1, 512, 160, 512);
    fc_kernel<1><<<dim3(16, 8), 256>>>(p_r1, fc2_w, fc2_b, p_r2, 512, 512, 1024);
    fc_kernel<2><<<dim3(13, 8), 256>>>(p_r2, fc3_w, fc3_b, out + 81920, 512, 1024, 784);
}

// round 8
// speedup vs baseline: 1.0342x; 1.0342x over previous
#include <cuda_runtime.h>
#include <cuda_bf16.h>
#include <math.h>
#include <stdint.h>

// ---------------- problem constants ----------------
#define BATCH 512
#define NPRIM 32
#define NCLASS 10

// ---------------- scratch (static device memory; no allocs allowed) ----------------
// conv1 output as bf16 hi/lo split, layout [b][pixel(400)][ic(256)]
__device__ __align__(256) unsigned short g_h1h[BATCH * 400 * 256];   // 100 MB
__device__ __align__(256) unsigned short g_h1l[BATCH * 400 * 256];   // 100 MB
// prim weights prepacked: [kpos25][chunk4][oc256][ic64] bf16 hi/lo
__device__ __align__(256) unsigned short g_Wph[25 * 4 * 256 * 64];   // 3.3 MB
__device__ __align__(256) unsigned short g_Wpl[25 * 4 * 256 * 64];   // 3.3 MB
__device__ float g_cwT[8 * 25 * 256];                    // conv_w transposed [c*25+k][oc]
__device__ float g_p[BATCH * NPRIM * 8 * 64];            // primary caps acts [b][i][a][pos]
__device__ float g_votes2[BATCH * 4 * 32 * 256];         // [b][pos][i][oc]
__device__ float g_c[BATCH * 32 * 8 * 4];                // [b][o][a][pos]
__device__ float g_masked[BATCH * 160];
__device__ float g_r1[BATCH * 512];
__device__ float g_r2[BATCH * 1024];

// ---------------- f32x2 helpers ----------------
__device__ __forceinline__ unsigned long long bcast2(float v) {
    unsigned long long r;
    asm("mov.b64 %0, {%1, %1};" : "=l"(r) : "f"(v));
    return r;
}
__device__ __forceinline__ void fma2(unsigned long long& acc, unsigned long long a,
                                     unsigned long long b) {
    asm("fma.rn.f32x2 %0, %1, %2, %0;" : "+l"(acc) : "l"(a), "l"(b));
}
__device__ __forceinline__ float2 unpk(unsigned long long v) {
    float2 r;
    asm("mov.b64 {%0, %1}, %2;" : "=f"(r.x), "=f"(r.y) : "l"(v));
    return r;
}

// ---------------- cp.async helpers ----------------
__device__ __forceinline__ void cp16(void* smem, const void* g) {
    unsigned s;
    asm("{ .reg .u64 t; cvta.to.shared.u64 t, %1; cvt.u32.u64 %0, t; }"
        : "=r"(s) : "l"(smem));
    asm volatile("cp.async.cg.shared.global [%0], [%1], 16;" :: "r"(s), "l"(g));
}
__device__ __forceinline__ void cp_commit() { asm volatile("cp.async.commit_group;"); }
__device__ __forceinline__ void cp_wait0() {
    asm volatile("cp.async.wait_group 0;" ::: "memory");
}

// ---------------- mma.sync bf16 + ldmatrix (sm_80+ legacy tensor path) ----------------
__device__ __forceinline__ void mma_bf16(float* d, const uint32_t* a, uint32_t b0,
                                         uint32_t b1) {
    asm volatile(
        "mma.sync.aligned.m16n8k16.row.col.f32.bf16.bf16.f32 "
        "{%0,%1,%2,%3}, {%4,%5,%6,%7}, {%8,%9}, {%0,%1,%2,%3};"
        : "+f"(d[0]), "+f"(d[1]), "+f"(d[2]), "+f"(d[3])
        : "r"(a[0]), "r"(a[1]), "r"(a[2]), "r"(a[3]), "r"(b0), "r"(b1));
}
__device__ __forceinline__ void ldm_x4(uint32_t* r, uint32_t addr) {
    asm volatile("ldmatrix.sync.aligned.m8n8.x4.shared.b16 {%0,%1,%2,%3}, [%4];"
        : "=r"(r[0]), "=r"(r[1]), "=r"(r[2]), "=r"(r[3]) : "r"(addr));
}
__device__ __forceinline__ uint32_t smem_u32(const void* p) {
    uint32_t a;
    asm("{ .reg .u64 t; cvta.to.shared.u64 t, %1; cvt.u32.u64 %0, t; }" : "=r"(a) : "l"(p));
    return a;
}

// ---------------- weight transpose: w[oc][ick] -> wt[ick][oc] ----------------
__global__ void transpose_oc(const float* __restrict__ w, float* __restrict__ wt,
                             int OC, int ICK) {
    int idx = blockIdx.x * 256 + threadIdx.x;
    if (idx >= OC * ICK) return;
    int ick = idx / OC, oc = idx % OC;
    wt[idx] = w[oc * ICK + ick];
}

// ---------------- prepack prim weights: [kpos][chunk][oc][ic64] bf16 hi/lo ------------
__global__ void prepack_W(const float* __restrict__ w) {
    int idx = blockIdx.x * 256 + threadIdx.x;
    if (idx >= 25 * 4 * 256 * 64) return;
    int ic = idx & 63;
    int oc = (idx >> 6) & 255;
    int chunk = (idx >> 14) & 3;
    int kpos = idx >> 16;
    float v = w[oc * 6400 + (chunk * 64 + ic) * 25 + kpos];
    __nv_bfloat16 hi = __float2bfloat16(v);
    __nv_bfloat16 lo = __float2bfloat16(v - __bfloat162float(hi));
    g_Wph[idx] = __bfloat16_as_ushort(hi);
    g_Wpl[idx] = __bfloat16_as_ushort(lo);
}

// ---------------- conv1 + relu (f32x2), writes bf16 hi/lo [b][pix][ic] ----------------
__global__ __launch_bounds__(256) void conv1_kernel(
    const float* __restrict__ x, const float* __restrict__ w,
    const float* __restrict__ bias) {
    __shared__ float sx[784];
    __shared__ float sw2[81 * 16];
    __shared__ float sb[16];
    int b = blockIdx.x, g = blockIdx.y, tid = threadIdx.x;
    for (int i = tid; i < 784; i += 256) sx[i] = x[b * 784 + i];
    for (int i = tid; i < 81 * 16; i += 256) {
        int k = i >> 4, c = i & 15;
        sw2[i] = w[(g * 16 + c) * 81 + k];
    }
    if (tid < 16) sb[tid] = bias[g * 16 + tid];
    __syncthreads();

    int p0 = tid;
    int p1 = tid + 256;
    bool has1 = (p1 < 400);
    int p1c = has1 ? p1 : 0;
    int y0 = p0 / 20, x0 = p0 % 20;
    int y1 = p1c / 20, x1 = p1c % 20;
    unsigned long long a0[8], a1[8];
#pragma unroll
    for (int j = 0; j < 8; j++) { a0[j] = 0ULL; a1[j] = 0ULL; }
#pragma unroll
    for (int kh = 0; kh < 9; kh++) {
#pragma unroll
        for (int kw = 0; kw < 9; kw++) {
            unsigned long long d0 = bcast2(sx[(y0 + kh) * 28 + x0 + kw]);
            unsigned long long d1 = bcast2(sx[(y1 + kh) * 28 + x1 + kw]);
            int k = kh * 9 + kw;
            const ulonglong2* wp = (const ulonglong2*)&sw2[k * 16];
            ulonglong2 wA = wp[0], wB = wp[1], wC = wp[2], wD = wp[3];
            fma2(a0[0], d0, wA.x); fma2(a0[1], d0, wA.y);
            fma2(a0[2], d0, wB.x); fma2(a0[3], d0, wB.y);
            fma2(a0[4], d0, wC.x); fma2(a0[5], d0, wC.y);
            fma2(a0[6], d0, wD.x); fma2(a0[7], d0, wD.y);
            fma2(a1[0], d1, wA.x); fma2(a1[1], d1, wA.y);
            fma2(a1[2], d1, wB.x); fma2(a1[3], d1, wB.y);
            fma2(a1[4], d1, wC.x); fma2(a1[5], d1, wC.y);
            fma2(a1[6], d1, wD.x); fma2(a1[7], d1, wD.y);
        }
    }
#pragma unroll
    for (int half = 0; half < 2; half++) {
        if (half == 1 && !has1) break;
        int p = half ? p1 : p0;
        unsigned long long* A = half ? a1 : a0;
        uint32_t hw[8], lw[8];
#pragma unroll
        for (int j = 0; j < 8; j++) {
            float2 v = unpk(A[j]);
            float r0 = v.x + sb[2 * j];     r0 = r0 > 0.f ? r0 : 0.f;
            float r1 = v.y + sb[2 * j + 1]; r1 = r1 > 0.f ? r1 : 0.f;
            __nv_bfloat16 h0 = __float2bfloat16(r0);
            __nv_bfloat16 h1 = __float2bfloat16(r1);
            __nv_bfloat16 l0 = __float2bfloat16(r0 - __bfloat162float(h0));
            __nv_bfloat16 l1 = __float2bfloat16(r1 - __bfloat162float(h1));
            hw[j] = (uint32_t)__bfloat16_as_ushort(h0) |
                    ((uint32_t)__bfloat16_as_ushort(h1) << 16);
            lw[j] = (uint32_t)__bfloat16_as_ushort(l0) |
                    ((uint32_t)__bfloat16_as_ushort(l1) << 16);
        }
        size_t base = ((size_t)b * 400 + p) * 256 + g * 16;
        uint4* dh = (uint4*)&g_h1h[base];
        uint4* dl = (uint4*)&g_h1l[base];
        dh[0] = make_uint4(hw[0], hw[1], hw[2], hw[3]);
        dh[1] = make_uint4(hw[4], hw[5], hw[6], hw[7]);
        dl[0] = make_uint4(lw[0], lw[1], lw[2], lw[3]);
        dl[1] = make_uint4(lw[4], lw[5], lw[6], lw[7]);
    }
}

// ---------------- primary caps conv via mma.sync + ldmatrix (R6 shape, 1 sync/step) ---
// grid 256 (2 batches/block), 512 threads (16 warps: warpM 0/1 x warpN 0..7 of 32 oc).
// 100 k-steps: (kpos 0..24) x (ic chunk 0..3, 64 ic each). A/B tiles pitch 144 B.
#define PITCH 144
#define OFF_AH 0
#define OFF_AL 18432                   // 128*144
#define OFF_BH 36864
#define OFF_BL 73728                   // OFF_BH + 256*144
#define PBUF 110592
#define PRIM_SMEM (2 * PBUF)           // 221184

extern __shared__ char psmem[];

__device__ __forceinline__ void prim_load_step(int buf, int s, int tid, int b0) {
    int kpos = s >> 2, chunk = s & 3;
    int kh = kpos / 5, kw = kpos - kh * 5;
    char* base = psmem + buf * PBUF;
    // A: 128 rows x 128B from g_h1h/g_h1l
#pragma unroll
    for (int ii = 0; ii < 2; ii++) {
        int i = tid + ii * 512;          // 0..1023
        int r = i >> 3, seg = i & 7;
        int batch = r >> 6, pos = r & 63;
        int y = pos >> 3, xx = pos & 7;
        int pix = (2 * y + kh) * 20 + 2 * xx + kw;
        size_t src = ((size_t)(b0 + batch) * 400 + pix) * 256 + chunk * 64 + seg * 8;
        char* d = base + r * PITCH + seg * 16;
        cp16(d + OFF_AH, &g_h1h[src]);
        cp16(d + OFF_AL, &g_h1l[src]);
    }
    // B: 256 rows x 128B from g_Wph/g_Wpl
    size_t wbase = (size_t)s * 16384;    // (kpos*4+chunk)*256*64
#pragma unroll
    for (int ii = 0; ii < 4; ii++) {
        int i = tid + ii * 512;          // 0..2047
        int r = i >> 3, seg = i & 7;
        size_t src = wbase + r * 64 + seg * 8;
        char* d = base + r * PITCH + seg * 16;
        cp16(d + OFF_BH, &g_Wph[src]);
        cp16(d + OFF_BL, &g_Wpl[src]);
    }
}

__global__ __launch_bounds__(512, 1) void prim_mma_kernel(const float* __restrict__ prim_bias) {
    int tid = threadIdx.x;
    int b0 = blockIdx.x * 2;
    int wid = tid >> 5, lane = tid & 31;
    int g = lane >> 2, c = lane & 3;
    int warpM = wid & 1;       // rows 0-63 / 64-127
    int warpN = wid >> 1;      // 0..7 -> oc slice of 32

    uint32_t sbase = smem_u32(psmem);
    uint32_t aOff = (uint32_t)(warpM * 64 + (lane & 15)) * PITCH + ((lane >> 4) << 4);
    uint32_t bRow = (uint32_t)(warpN * 32 + (lane & 7) + ((lane & 16) >> 1));
    uint32_t bOff = bRow * PITCH + ((lane & 8) ? 16u : 0u);

    float acc[4][4][4];
#pragma unroll
    for (int mt = 0; mt < 4; mt++)
#pragma unroll
        for (int j = 0; j < 4; j++)
#pragma unroll
            for (int q = 0; q < 4; q++) acc[mt][j][q] = 0.f;

    // prologue: step 0 in flight
    prim_load_step(0, 0, tid, b0);
    cp_commit();

    for (int s = 0; s < 100; s++) {
        int buf = s & 1;
        cp_wait0();          // step s resident (only pending group)
        __syncthreads();     // also proves all warps finished reading buf^1 (step s-1)
        if (s + 1 < 100) {
            prim_load_step(buf ^ 1, s + 1, tid, b0);
            cp_commit();
        }
        uint32_t tbase = sbase + buf * PBUF;
        uint32_t aBase = tbase + OFF_AH + aOff;
        uint32_t bBase = tbase + OFF_BH + bOff;
#pragma unroll
        for (int kk = 0; kk < 4; kk++) {
            uint32_t bh[2][4], bl[2][4];
#pragma unroll
            for (int np = 0; np < 2; np++) {
                ldm_x4(bh[np], bBase + np * (16 * PITCH) + kk * 32);
                ldm_x4(bl[np], bBase + (OFF_BL - OFF_BH) + np * (16 * PITCH) + kk * 32);
            }
#pragma unroll
            for (int mt = 0; mt < 4; mt++) {
                uint32_t ah[4], al[4];
                ldm_x4(ah, aBase + mt * (16 * PITCH) + kk * 32);
                ldm_x4(al, aBase + (OFF_AL - OFF_AH) + mt * (16 * PITCH) + kk * 32);
#pragma unroll
                for (int np = 0; np < 2; np++)
#pragma unroll
                    for (int nt = 0; nt < 2; nt++) {
                        float* d = acc[mt][np * 2 + nt];
                        mma_bf16(d, ah, bh[np][nt * 2], bh[np][nt * 2 + 1]);
                        mma_bf16(d, ah, bl[np][nt * 2], bl[np][nt * 2 + 1]);
                        mma_bf16(d, al, bh[np][nt * 2], bh[np][nt * 2 + 1]);
                    }
            }
        }
    }

    // fused epilogue: route=1/32, +bias, squash over 8 atoms (quad shfl reduction)
    int b_ = b0 + warpM;
#pragma unroll
    for (int mt = 0; mt < 4; mt++) {
        int pos1 = mt * 16 + g;
        int pos2 = pos1 + 8;
#pragma unroll
        for (int j = 0; j < 4; j++) {
            int caps = warpN * 4 + j;
            float bv0 = __ldg(&prim_bias[caps * 8 + 2 * c]);
            float bv1 = __ldg(&prim_bias[caps * 8 + 2 * c + 1]);
            float v0 = acc[mt][j][0] * (1.f / 32.f) + bv0;
            float v1 = acc[mt][j][1] * (1.f / 32.f) + bv1;
            float v2 = acc[mt][j][2] * (1.f / 32.f) + bv0;
            float v3 = acc[mt][j][3] * (1.f / 32.f) + bv1;
            float na = v0 * v0 + v1 * v1;
            float nb = v2 * v2 + v3 * v3;
            na += __shfl_xor_sync(0xFFFFFFFFu, na, 1);
            na += __shfl_xor_sync(0xFFFFFFFFu, na, 2);
            nb += __shfl_xor_sync(0xFFFFFFFFu, nb, 1);
            nb += __shfl_xor_sync(0xFFFFFFFFu, nb, 2);
            float fa = (na / (1.f + na)) * rsqrtf(na + 1e-8f);
            float fb = (nb / (1.f + nb)) * rsqrtf(nb + 1e-8f);
            size_t base = ((size_t)(b_ * 32 + caps) * 8) * 64;
            g_p[base + (2 * c) * 64 + pos1] = v0 * fa;
            g_p[base + (2 * c + 1) * 64 + pos1] = v1 * fa;
            g_p[base + (2 * c) * 64 + pos2] = v2 * fb;
            g_p[base + (2 * c + 1) * 64 + pos2] = v3 * fb;
        }
    }
}

// ---------------- conv-caps votes (f32x2; weights via L2, smem 64KB -> occ 3) ---------
__global__ __launch_bounds__(256) void cc_votes_kernel() {
    extern __shared__ float smem[];
    float* sp = smem;                     // [i32][c8][8][8] = 16384 floats
    int b = blockIdx.x, tid = threadIdx.x;
    for (int idx = tid; idx < 16384; idx += 256) sp[idx] = g_p[b * 16384 + idx];
    __syncthreads();

    int ocg = tid & 7;
    int i = tid >> 3;
#pragma unroll 1
    for (int occ = 0; occ < 4; occ++) {
        const float* wsrc = &g_cwT[occ * 64 + ocg * 8];
        unsigned long long acc[4][4];
#pragma unroll
        for (int p = 0; p < 4; p++)
#pragma unroll
            for (int j = 0; j < 4; j++) acc[p][j] = 0ULL;
#pragma unroll 1
        for (int cc = 0; cc < 8; cc++) {
            const float* spc = &sp[(i * 8 + cc) * 64];
#pragma unroll
            for (int kh = 0; kh < 5; kh++) {
#pragma unroll
                for (int kw = 0; kw < 5; kw++) {
                    int k = cc * 25 + kh * 5 + kw;
                    float4 w0 = __ldg((const float4*)(wsrc + k * 256));
                    float4 w1 = __ldg((const float4*)(wsrc + k * 256 + 4));
                    unsigned long long wx, wy, wz;
                    asm("mov.b64 %0, {%1, %2};" : "=l"(wx) : "f"(w0.x), "f"(w0.y));
                    asm("mov.b64 %0, {%1, %2};" : "=l"(wy) : "f"(w0.z), "f"(w0.w));
                    asm("mov.b64 %0, {%1, %2};" : "=l"(wz) : "f"(w1.x), "f"(w1.y));
                    unsigned long long ww;
                    asm("mov.b64 %0, {%1, %2};" : "=l"(ww) : "f"(w1.z), "f"(w1.w));
                    unsigned long long d00 = bcast2(spc[kh * 8 + kw]);
                    unsigned long long d01 = bcast2(spc[kh * 8 + kw + 2]);
                    unsigned long long d10 = bcast2(spc[(kh + 2) * 8 + kw]);
                    unsigned long long d11 = bcast2(spc[(kh + 2) * 8 + kw + 2]);
                    fma2(acc[0][0], d00, wx); fma2(acc[0][1], d00, wy);
                    fma2(acc[0][2], d00, wz); fma2(acc[0][3], d00, ww);
                    fma2(acc[1][0], d01, wx); fma2(acc[1][1], d01, wy);
                    fma2(acc[1][2], d01, wz); fma2(acc[1][3], d01, ww);
                    fma2(acc[2][0], d10, wx); fma2(acc[2][1], d10, wy);
                    fma2(acc[2][2], d10, wz); fma2(acc[2][3], d10, ww);
                    fma2(acc[3][0], d11, wx); fma2(acc[3][1], d11, wy);
                    fma2(acc[3][2], d11, wz); fma2(acc[3][3], d11, ww);
                }
            }
        }
#pragma unroll
        for (int p = 0; p < 4; p++) {
            float2 q0 = unpk(acc[p][0]), q1 = unpk(acc[p][1]);
            float2 q2 = unpk(acc[p][2]), q3 = unpk(acc[p][3]);
            float4* dst = (float4*)&g_votes2[((b * 4 + p) * 32 + i) * 256 + occ * 64 + ocg * 8];
            dst[0] = make_float4(q0.x, q0.y, q1.x, q1.y);
            dst[1] = make_float4(q2.x, q2.y, q3.x, q3.y);
        }
    }
}

// ---------------- conv-caps routing (3 iters) ----------------
__global__ __launch_bounds__(256) void cc_routing_kernel(const float* __restrict__ conv_bias) {
    __shared__ float sv[8192];
    __shared__ float slog[1024];
    __shared__ float sroute[1024];
    __shared__ float spre[256];
    __shared__ float sact[256];
    int blk = blockIdx.x;
    int b = blk >> 2, pos = blk & 3;
    int tid = threadIdx.x;
    for (int idx = tid; idx < 8192; idx += 256)
        sv[idx] = g_votes2[(b * 4 + pos) * 8192 + idx];
    for (int e = tid; e < 1024; e += 256) slog[e] = 0.f;
    __syncthreads();

    for (int it = 0; it < 3; it++) {
        if (tid < 32) {
            int i = tid;
            float m = slog[i * 32];
            for (int o = 1; o < 32; o++) m = fmaxf(m, slog[i * 32 + o]);
            float z = 0.f;
            for (int o = 0; o < 32; o++) {
                float e = expf(slog[i * 32 + o] - m);
                sroute[i * 32 + o] = e;
                z += e;
            }
            float inv = 1.f / z;
            for (int o = 0; o < 32; o++) sroute[i * 32 + o] *= inv;
        }
        __syncthreads();
        {
            int o = tid >> 3, a = tid & 7;
            float s = conv_bias[o * 8 + a];
            for (int i = 0; i < 32; i++)
                s += sroute[i * 32 + o] * sv[(i * 32 + o) * 8 + a];
            spre[tid] = s;
        }
        __syncthreads();
        {
            int o = tid >> 3;
            float n2 = 0.f;
#pragma unroll
            for (int a = 0; a < 8; a++) { float v = spre[o * 8 + a]; n2 += v * v; }
            float f = (n2 / (1.f + n2)) * rsqrtf(n2 + 1e-8f);
            sact[tid] = spre[tid] * f;
        }
        __syncthreads();
        if (it < 2) {
            for (int e = tid; e < 1024; e += 256) {
                int o = e & 31;
                float d = 0.f;
#pragma unroll
                for (int a = 0; a < 8; a++) d += sv[e * 8 + a] * sact[o * 8 + a];
                slog[e] += d;
            }
            __syncthreads();
        }
    }
    {
        int o = tid >> 3, a = tid & 7;
        g_c[((b * 32 + o) * 8 + a) * 4 + pos] = sact[tid];
    }
}

// ---------------- digit caps: votes + routing + mask ----------------
__global__ __launch_bounds__(256) void digit_kernel(
    const float* __restrict__ digit_w, const float* __restrict__ digit_bias,
    const float* __restrict__ y, float* __restrict__ out_dcap) {
    __shared__ float smem[11264];
    float* sc = smem;
    float* sdw = smem + 1024;
    float* sv = smem + 6144;
    int b = blockIdx.x, tid = threadIdx.x;
    for (int idx = tid; idx < 1024; idx += 256) sc[idx] = g_c[b * 1024 + idx];
    for (int idx = tid; idx < 5120; idx += 256) sdw[idx] = digit_w[idx];
    __syncthreads();
    for (int idx = tid; idx < 5120; idx += 256) {
        int i = idx / 160, oa = idx % 160;
        float s = 0.f;
        const float* ci = &sc[i * 32];
        const float* wv = &sdw[oa * 32];
#pragma unroll
        for (int z = 0; z < 32; z++) s += ci[z] * wv[z];
        sv[(i * 10 + (oa >> 4)) * 16 + (oa & 15)] = s;
    }
    __syncthreads();
    float* slog = smem;
    float* sroute = smem + 320;
    float* spre = smem + 640;
    float* sact = smem + 800;
    float* sbias = smem + 960;
    for (int e = tid; e < 320; e += 256) slog[e] = 0.f;
    if (tid < 160) sbias[tid] = digit_bias[tid];
    __syncthreads();

    for (int it = 0; it < 3; it++) {
        if (tid < 32) {
            int i = tid;
            float m = slog[i * 10];
            for (int o = 1; o < 10; o++) m = fmaxf(m, slog[i * 10 + o]);
            float z = 0.f;
            for (int o = 0; o < 10; o++) {
                float e = expf(slog[i * 10 + o] - m);
                sroute[i * 10 + o] = e;
                z += e;
            }
            float inv = 1.f / z;
            for (int o = 0; o < 10; o++) sroute[i * 10 + o] *= inv;
        }
        __syncthreads();
        if (tid < 160) {
            int o = tid >> 4, a = tid & 15;
            float s = sbias[tid];
            for (int i = 0; i < 32; i++)
                s += sroute[i * 10 + o] * sv[(i * 10 + o) * 16 + a];
            spre[tid] = s;
        }
        __syncthreads();
        if (tid < 160) {
            int o = tid >> 4;
            float n2 = 0.f;
#pragma unroll
            for (int a = 0; a < 16; a++) { float v = spre[o * 16 + a]; n2 += v * v; }
            float f = (n2 / (1.f + n2)) * rsqrtf(n2 + 1e-8f);
            sact[tid] = spre[tid] * f;
        }
        __syncthreads();
        if (it < 2) {
            for (int e = tid; e < 320; e += 256) {
                int o = e % 10;
                float d = 0.f;
#pragma unroll
                for (int a = 0; a < 16; a++) d += sv[e * 16 + a] * sact[o * 16 + a];
                slog[e] += d;
            }
            __syncthreads();
        }
    }
    if (tid < 160) {
        int o = tid >> 4;
        float v = sact[tid];
        out_dcap[b * 160 + tid] = v;
        g_masked[b * 160 + tid] = v * y[b * 10 + o];
    }
}

// ---------------- FC: C = act(A @ W + bias) ----------------
template <int ACT>
__global__ __launch_bounds__(256) void fc_kernel(
    const float* __restrict__ A, const float* __restrict__ W,
    const float* __restrict__ bias, float* __restrict__ C,
    int M, int K, int N) {
    __shared__ float As[16][64];
    __shared__ float Ws[16][64];
    int m0 = blockIdx.y * 64, n0 = blockIdx.x * 64;
    int tid = threadIdx.x;
    int tr = tid >> 4, tc = tid & 15;
    float acc[4][4];
#pragma unroll
    for (int i = 0; i < 4; i++)
#pragma unroll
        for (int j = 0; j < 4; j++) acc[i][j] = 0.f;

    for (int k0 = 0; k0 < K; k0 += 16) {
        for (int l = tid; l < 1024; l += 256) {
            int ml = l >> 4, kl = l & 15;
            As[kl][ml] = A[(m0 + ml) * K + k0 + kl];
        }
        for (int l = tid; l < 1024; l += 256) {
            int kl = l >> 6, nl = l & 63;
            int n = n0 + nl;
            Ws[kl][nl] = (n < N) ? W[(k0 + kl) * N + n] : 0.f;
        }
        __syncthreads();
#pragma unroll
        for (int kk = 0; kk < 16; kk++) {
            float4 a4 = *(const float4*)&As[kk][tr * 4];
            float4 b4 = *(const float4*)&Ws[kk][tc * 4];
            float av[4] = {a4.x, a4.y, a4.z, a4.w};
            float bv[4] = {b4.x, b4.y, b4.z, b4.w};
#pragma unroll
            for (int i = 0; i < 4; i++)
#pragma unroll
                for (int j = 0; j < 4; j++) acc[i][j] += av[i] * bv[j];
        }
        __syncthreads();
    }
#pragma unroll
    for (int i = 0; i < 4; i++) {
        int m = m0 + tr * 4 + i;
#pragma unroll
        for (int j = 0; j < 4; j++) {
            int n = n0 + tc * 4 + j;
            if (n < N) {
                float v = acc[i][j] + bias[n];
                if (ACT == 1) v = v > 0.f ? v : 0.f;
                if (ACT == 2) v = 1.f / (1.f + expf(-v));
                C[m * N + n] = v;
            }
        }
    }
}

// ---------------- launcher ----------------
extern "C" void kernel_launch(void* const* d_in, const int* in_sizes, int n_in,
                              void* d_out, int out_size) {
    const float* x = (const float*)d_in[0];
    const float* y = (const float*)d_in[1];
    const float* conv1_w = (const float*)d_in[2];
    const float* conv1_b = (const float*)d_in[3];
    const float* prim_w = (const float*)d_in[4];
    const float* prim_bias = (const float*)d_in[5];
    const float* conv_w = (const float*)d_in[6];
    const float* conv_bias = (const float*)d_in[7];
    const float* digit_w = (const float*)d_in[8];
    const float* digit_bias = (const float*)d_in[9];
    const float* fc1_w = (const float*)d_in[10];
    const float* fc1_b = (const float*)d_in[11];
    const float* fc2_w = (const float*)d_in[12];
    const float* fc2_b = (const float*)d_in[13];
    const float* fc3_w = (const float*)d_in[14];
    const float* fc3_b = (const float*)d_in[15];
    float* out = (float*)d_out;              // [0:81920) dcap, [81920:483328) recon

    static float *p_masked = nullptr, *p_r1 = nullptr, *p_r2 = nullptr;
    static float *g_cwT_p = nullptr;
    static bool attrs_set = false;
    if (!p_masked) {
        cudaGetSymbolAddress((void**)&p_masked, g_masked);
        cudaGetSymbolAddress((void**)&p_r1, g_r1);
        cudaGetSymbolAddress((void**)&p_r2, g_r2);
        cudaGetSymbolAddress((void**)&g_cwT_p, g_cwT);
    }
    if (!attrs_set) {
        cudaFuncSetAttribute(prim_mma_kernel, cudaFuncAttributeMaxDynamicSharedMemorySize,
                             PRIM_SMEM);
        cudaFuncSetAttribute(cc_votes_kernel, cudaFuncAttributeMaxDynamicSharedMemorySize,
                             16384 * 4);
        attrs_set = true;
    }

    // weight prep
    prepack_W<<<(25 * 4 * 256 * 64 + 255) / 256, 256>>>(prim_w);
    transpose_oc<<<200, 256>>>(conv_w, g_cwT_p, 256, 200);

    // conv1 + relu (writes bf16 hi/lo, pixel-major)
    conv1_kernel<<<dim3(512, 16), 256>>>(x, conv1_w, conv1_b);

    // primary caps conv via mma.sync + ldmatrix (single sync/step) + fused squash
    prim_mma_kernel<<<256, 512, PRIM_SMEM>>>(prim_bias);

    // conv caps votes (weights via L2; 64KB smem -> occupancy 3)
    cc_votes_kernel<<<512, 256, 16384 * 4>>>();

    // conv caps routing
    cc_routing_kernel<<<2048, 256>>>(conv_bias);

    // digit caps
    digit_kernel<<<512, 256>>>(digit_w, digit_bias, y, out);

    // FC reconstruction chain
    fc_kernel<1><<<dim3(8, 8), 256>>>(p_masked, fc1_w, fc1_b, p_r1, 512, 160, 512);
    fc_kernel<1><<<dim3(16, 8), 256>>>(p_r1, fc2_w, fc2_b, p_r2, 512, 512, 1024);
    fc_kernel<2><<<dim3(13, 8), 256>>>(p_r2, fc3_w, fc3_b, out + 81920, 512, 1024, 784);
}